// round 15
// baseline (speedup 1.0000x reference)
#include <cuda_runtime.h>
#include <cuda_bf16.h>
#include <cuda_fp16.h>
#include <stdint.h>

// GCN 2-layer, N=50000, E=640000, 128 -> 128(relu) -> 40.
// y = dinv*(x@W) via bf16x3 tensor-core GEMM (fp16 feature storage);
// agg via CSR warp-gather (fp32 accum); gather1 fused with layer-2 GEMM.

#define NN 50000
#define NE 640000

// ---- scratch (device globals; allocation forbidden) ----
__device__ int   g_is32;
__device__ int   g_eidx[NE];
__device__ int   g_rowptr[NN + 1];
__device__ int   g_cursor[NN];
__device__ int   g_rowtmp[NN];
__device__ int   g_bsum[256];
__device__ int   g_boff[256];
__device__ int   g_deg[NN];
__device__ float g_dinv[NN];
__device__ __align__(16) __half g_y1h[NN * 128];   // layer1 scaled GEMM out (fp16)
__device__ __align__(16) __half g_y2h[NN * 40];    // layer2 scaled GEMM out (fp16)
__device__ __align__(4) __nv_bfloat16 g_W1h[128 * 128], g_W1l[128 * 128];
__device__ __align__(4) __nv_bfloat16 g_W2h[128 * 40],  g_W2l[128 * 40];

// ---------------- prologue ----------------
__global__ void k_init(const int* __restrict__ ei32, int nn) {
    int t = threadIdx.x;
    int i = blockIdx.x * 256 + t;
    if (i < nn) g_deg[i] = 0;
    if (blockIdx.x == 0) {
        __shared__ int any;
        if (t == 0) any = 0;
        __syncthreads();
        if (ei32[2 * t + 1] != 0) any = 1;   // int64 high halves all 0
        __syncthreads();
        if (t == 0) g_is32 = any;
    }
}

__global__ void k_count(const int* __restrict__ ei32, int ne, int nn) {
    int e = blockIdx.x * blockDim.x + threadIdx.x;
    if (e >= ne) return;
    int d = g_is32 ? ei32[ne + e] : ei32[2 * ne + 2 * e];
    d = ((unsigned)d < (unsigned)nn) ? d : 0;
    atomicAdd(&g_deg[d], 1);
}

__device__ __forceinline__ int blk_scan_incl(int v, int t) {
    int x = v;
#pragma unroll
    for (int o = 1; o < 32; o <<= 1) {
        int y = __shfl_up_sync(0xFFFFFFFFu, x, o);
        if ((t & 31) >= o) x += y;
    }
    __shared__ int ws[8];
    if ((t & 31) == 31) ws[t >> 5] = x;
    __syncthreads();
    if (t < 8) {
        int y = ws[t], z = y;
#pragma unroll
        for (int o = 1; o < 8; o <<= 1) {
            int u = __shfl_up_sync(0xFFu, z, o);
            if (t >= o) z += u;
        }
        ws[t] = z - y;
    }
    __syncthreads();
    return x + ws[t >> 5];
}

__global__ void k_scan1(int nn) {
    int t = threadIdx.x;
    int i = blockIdx.x * 256 + t;
    int v = (i < nn) ? g_deg[i] : 0;
    int incl = blk_scan_incl(v, t);
    if (i < nn) g_rowtmp[i] = incl - v;
    if (t == 255) g_bsum[blockIdx.x] = incl;
}

__global__ void k_scan2(int nb) {
    int t = threadIdx.x;
    int v = (t < nb) ? g_bsum[t] : 0;
    int incl = blk_scan_incl(v, t);
    g_boff[t] = incl - v;
}

// rowptr/cursor/dinv + weight split (fused). MUST be launched with >= nn threads.
__global__ void k_scan3(const float* __restrict__ W1, const float* __restrict__ W2,
                        int nn, int ne) {
    int i = blockIdx.x * blockDim.x + threadIdx.x;
    if (i < nn) {
        int rp = g_rowtmp[i] + g_boff[i >> 8];
        g_rowptr[i] = rp;
        g_cursor[i] = rp;
        g_dinv[i] = rsqrtf((float)(g_deg[i] + 1));
    }
    if (i == 0) g_rowptr[nn] = ne;
    if (i < 128 * 128) {
        float v = W1[i];
        __nv_bfloat16 h = __float2bfloat16(v);
        g_W1h[i] = h;
        g_W1l[i] = __float2bfloat16(v - __bfloat162float(h));
    }
    if (i < 128 * 40) {
        float v = W2[i];
        __nv_bfloat16 h = __float2bfloat16(v);
        g_W2h[i] = h;
        g_W2l[i] = __float2bfloat16(v - __bfloat162float(h));
    }
}

__global__ void k_fill(const int* __restrict__ ei32, int ne, int nn) {
    int e = blockIdx.x * blockDim.x + threadIdx.x;
    if (e >= ne) return;
    int s, d;
    if (g_is32) { s = ei32[e];     d = ei32[ne + e]; }
    else        { s = ei32[2 * e]; d = ei32[2 * ne + 2 * e]; }
    s = ((unsigned)s < (unsigned)nn) ? s : 0;
    d = ((unsigned)d < (unsigned)nn) ? d : 0;
    int pos = atomicAdd(&g_cursor[d], 1);
    g_eidx[pos] = s;
}

// ---------------- MMA helpers ----------------
__device__ __forceinline__ uint32_t s2u(const void* p) {
    return (uint32_t)__cvta_generic_to_shared(p);
}
__device__ __forceinline__ uint32_t pack2(float a, float b) {
    __nv_bfloat162 t = __floats2bfloat162_rn(a, b);
    return *(uint32_t*)&t;
}
__device__ __forceinline__ void ldsm_x4(uint32_t a[4], uint32_t addr) {
    asm volatile("ldmatrix.sync.aligned.m8n8.x4.shared.b16 {%0,%1,%2,%3},[%4];"
                 : "=r"(a[0]), "=r"(a[1]), "=r"(a[2]), "=r"(a[3]) : "r"(addr));
}
__device__ __forceinline__ void ldsm_x2t(uint32_t b[2], uint32_t addr) {
    asm volatile("ldmatrix.sync.aligned.m8n8.x2.trans.shared.b16 {%0,%1},[%2];"
                 : "=r"(b[0]), "=r"(b[1]) : "r"(addr));
}
__device__ __forceinline__ void mma16816(float d[4], const uint32_t a[4], const uint32_t b[2]) {
    asm volatile("mma.sync.aligned.m16n8k16.row.col.f32.bf16.bf16.f32 "
                 "{%0,%1,%2,%3},{%4,%5,%6,%7},{%8,%9},{%0,%1,%2,%3};"
                 : "+f"(d[0]), "+f"(d[1]), "+f"(d[2]), "+f"(d[3])
                 : "r"(a[0]), "r"(a[1]), "r"(a[2]), "r"(a[3]), "r"(b[0]), "r"(b[1]));
}

// core MMA over pre-filled smem tiles: out fp16, scaled by dinv
template <int NW, int XP, int WP>
__device__ __forceinline__ void mma_tile_store(
    const __nv_bfloat16* xh, const __nv_bfloat16* xl,
    const __nv_bfloat16* wh, const __nv_bfloat16* wl,
    __half* outp, int m_base, int nn, int tid)
{
    constexpr int NT = NW / 8;
    int warp = tid >> 5, lane = tid & 31;
    int mrow = warp * 16;

    float d[NT][4];
#pragma unroll
    for (int t = 0; t < NT; t++) { d[t][0] = d[t][1] = d[t][2] = d[t][3] = 0.f; }

    uint32_t xh_b = s2u(xh), xl_b = s2u(xl), wh_b = s2u(wh), wl_b = s2u(wl);
    uint32_t a_off = ((mrow + (lane & 15)) * XP + (lane >> 4) * 8) * 2;
    uint32_t b_lrow = (lane & 15);

#pragma unroll
    for (int ks = 0; ks < 8; ks++) {
        uint32_t ah[4], al[4];
        ldsm_x4(ah, xh_b + a_off + ks * 32);
        ldsm_x4(al, xl_b + a_off + ks * 32);
        uint32_t brow = ((ks * 16 + b_lrow) * WP) * 2;
#pragma unroll
        for (int nt = 0; nt < NT; nt++) {
            uint32_t bh[2], bl[2];
            ldsm_x2t(bh, wh_b + brow + nt * 16);
            ldsm_x2t(bl, wl_b + brow + nt * 16);
            mma16816(d[nt], ah, bh);
            mma16816(d[nt], ah, bl);
            mma16816(d[nt], al, bh);
        }
    }

    int r0 = m_base + mrow + (lane >> 2);
    int r1 = r0 + 8;
    int c0 = (lane & 3) * 2;
    float di0 = (r0 < nn) ? g_dinv[r0] : 0.f;
    float di1 = (r1 < nn) ? g_dinv[r1] : 0.f;
#pragma unroll
    for (int nt = 0; nt < NT; nt++) {
        int col = nt * 8 + c0;
        if (r0 < nn)
            *(__half2*)&outp[(size_t)r0 * NW + col] = __floats2half2_rn(d[nt][0] * di0, d[nt][1] * di0);
        if (r1 < nn)
            *(__half2*)&outp[(size_t)r1 * NW + col] = __floats2half2_rn(d[nt][2] * di1, d[nt][3] * di1);
    }
}

// ---------------- layer 1 GEMM: y1h = fp16(dinv * (x @ W1)) ----------------
__global__ void k_gemm1(const float* __restrict__ x, int nn) {
    constexpr int XP = 136, WP = 136;
    extern __shared__ __nv_bfloat16 sm[];
    __nv_bfloat16* xh = sm;
    __nv_bfloat16* xl = xh + 128 * XP;
    __nv_bfloat16* wh = xl + 128 * XP;
    __nv_bfloat16* wl = wh + 128 * WP;

    int tid = threadIdx.x;
    int m_base = blockIdx.x * 128;

    const uint32_t* wsh = (const uint32_t*)g_W1h;
    const uint32_t* wsl = (const uint32_t*)g_W1l;
    for (int i = tid; i < 128 * 128 / 2; i += 256) {
        int r = (2 * i) >> 7, c = (2 * i) & 127;
        *(uint32_t*)&wh[r * WP + c] = wsh[i];
        *(uint32_t*)&wl[r * WP + c] = wsl[i];
    }
    for (int i = tid; i < 128 * 32; i += 256) {
        int r = i >> 5, cq = i & 31;
        int row = m_base + r;
        float4 v = make_float4(0.f, 0.f, 0.f, 0.f);
        if (row < nn) v = ((const float4*)(x + (size_t)row * 128))[cq];
        float hx = __bfloat162float(__float2bfloat16(v.x));
        float hy = __bfloat162float(__float2bfloat16(v.y));
        float hz = __bfloat162float(__float2bfloat16(v.z));
        float hw = __bfloat162float(__float2bfloat16(v.w));
        *(uint2*)&xh[r * XP + cq * 4] = make_uint2(pack2(v.x, v.y), pack2(v.z, v.w));
        *(uint2*)&xl[r * XP + cq * 4] =
            make_uint2(pack2(v.x - hx, v.y - hy), pack2(v.z - hz, v.w - hw));
    }
    __syncthreads();
    mma_tile_store<128, XP, WP>(xh, xl, wh, wl, g_y1h, m_base, nn, tid);
}

// ---------------- fused: gather1 (h into smem, bf16 split) + layer2 GEMM ----------------
__global__ void k_mid(const float* __restrict__ b1, int nn) {
    constexpr int XP = 136, WP = 56, NW = 40;
    extern __shared__ __nv_bfloat16 sm[];
    __nv_bfloat16* xh = sm;
    __nv_bfloat16* xl = xh + 128 * XP;
    __nv_bfloat16* wh = xl + 128 * XP;
    __nv_bfloat16* wl = wh + 128 * WP;

    int tid = threadIdx.x;
    int warp = tid >> 5, lane = tid & 31;
    int m_base = blockIdx.x * 128;

    const uint32_t* wsh = (const uint32_t*)g_W2h;
    const uint32_t* wsl = (const uint32_t*)g_W2l;
    for (int i = tid; i < 128 * NW / 2; i += 256) {
        int r = (2 * i) / NW, c = (2 * i) % NW;
        *(uint32_t*)&wh[r * WP + c] = wsh[i];
        *(uint32_t*)&wl[r * WP + c] = wsl[i];
    }

    float4 bia = ((const float4*)b1)[lane];   // lane owns channels 4*lane..4*lane+3
#pragma unroll 1
    for (int j = 0; j < 16; j++) {
        int r = warp * 16 + j;
        int n = m_base + r;
        float4 acc = make_float4(0.f, 0.f, 0.f, 0.f);
        if (n < nn) {
            int beg = g_rowptr[n], end = g_rowptr[n + 1];
            uint2 sv = *(const uint2*)(g_y1h + (size_t)n * 128 + lane * 4);  // self loop
            float2 a0 = __half22float2(*(__half2*)&sv.x);
            float2 a1 = __half22float2(*(__half2*)&sv.y);
            acc = make_float4(a0.x, a0.y, a1.x, a1.y);
            int k = beg;
            for (; k + 3 < end; k += 4) {
                int s0 = g_eidx[k], s1 = g_eidx[k + 1], s2 = g_eidx[k + 2], s3 = g_eidx[k + 3];
                uint2 v0 = *(const uint2*)(g_y1h + (size_t)s0 * 128 + lane * 4);
                uint2 v1 = *(const uint2*)(g_y1h + (size_t)s1 * 128 + lane * 4);
                uint2 v2 = *(const uint2*)(g_y1h + (size_t)s2 * 128 + lane * 4);
                uint2 v3 = *(const uint2*)(g_y1h + (size_t)s3 * 128 + lane * 4);
                float2 p;
                p = __half22float2(*(__half2*)&v0.x); acc.x += p.x; acc.y += p.y;
                p = __half22float2(*(__half2*)&v0.y); acc.z += p.x; acc.w += p.y;
                p = __half22float2(*(__half2*)&v1.x); acc.x += p.x; acc.y += p.y;
                p = __half22float2(*(__half2*)&v1.y); acc.z += p.x; acc.w += p.y;
                p = __half22float2(*(__half2*)&v2.x); acc.x += p.x; acc.y += p.y;
                p = __half22float2(*(__half2*)&v2.y); acc.z += p.x; acc.w += p.y;
                p = __half22float2(*(__half2*)&v3.x); acc.x += p.x; acc.y += p.y;
                p = __half22float2(*(__half2*)&v3.y); acc.z += p.x; acc.w += p.y;
            }
            for (; k < end; k++) {
                int s = g_eidx[k];
                uint2 v = *(const uint2*)(g_y1h + (size_t)s * 128 + lane * 4);
                float2 p;
                p = __half22float2(*(__half2*)&v.x); acc.x += p.x; acc.y += p.y;
                p = __half22float2(*(__half2*)&v.y); acc.z += p.x; acc.w += p.y;
            }
            float di = g_dinv[n];
            acc.x = fmaxf(fmaf(di, acc.x, bia.x), 0.f);
            acc.y = fmaxf(fmaf(di, acc.y, bia.y), 0.f);
            acc.z = fmaxf(fmaf(di, acc.z, bia.z), 0.f);
            acc.w = fmaxf(fmaf(di, acc.w, bia.w), 0.f);
        }
        float hx = __bfloat162float(__float2bfloat16(acc.x));
        float hy = __bfloat162float(__float2bfloat16(acc.y));
        float hz = __bfloat162float(__float2bfloat16(acc.z));
        float hw = __bfloat162float(__float2bfloat16(acc.w));
        *(uint2*)&xh[r * XP + lane * 4] = make_uint2(pack2(acc.x, acc.y), pack2(acc.z, acc.w));
        *(uint2*)&xl[r * XP + lane * 4] =
            make_uint2(pack2(acc.x - hx, acc.y - hy), pack2(acc.z - hz, acc.w - hw));
    }
    __syncthreads();
    mma_tile_store<NW, XP, WP>(xh, xl, wh, wl, g_y2h, m_base, nn, tid);
}

// ---------------- layer 2 gather: out = dinv*(y2[n] + sum y2[src]) + b2 ----------------
__global__ void k_gather2(float* __restrict__ out, const float* __restrict__ b2, int nn) {
    int warp = (blockIdx.x * blockDim.x + threadIdx.x) >> 5;
    if (warp >= nn) return;
    int lane = threadIdx.x & 31;
    int n = warp;
    int beg = g_rowptr[n], end = g_rowptr[n + 1];
    int sub = lane / 10;
    int q = lane % 10;
    float4 acc = make_float4(0.f, 0.f, 0.f, 0.f);
    if (sub == 0) {
        uint2 v = *(const uint2*)(g_y2h + (size_t)n * 40 + q * 4);
        float2 p0 = __half22float2(*(__half2*)&v.x);
        float2 p1 = __half22float2(*(__half2*)&v.y);
        acc = make_float4(p0.x, p0.y, p1.x, p1.y);
    }
    int k = (sub < 3) ? (beg + sub) : end;
    for (; k + 3 < end; k += 6) {
        int s0 = g_eidx[k], s1 = g_eidx[k + 3];
        uint2 v0 = *(const uint2*)(g_y2h + (size_t)s0 * 40 + q * 4);
        uint2 v1 = *(const uint2*)(g_y2h + (size_t)s1 * 40 + q * 4);
        float2 p;
        p = __half22float2(*(__half2*)&v0.x); acc.x += p.x; acc.y += p.y;
        p = __half22float2(*(__half2*)&v0.y); acc.z += p.x; acc.w += p.y;
        p = __half22float2(*(__half2*)&v1.x); acc.x += p.x; acc.y += p.y;
        p = __half22float2(*(__half2*)&v1.y); acc.z += p.x; acc.w += p.y;
    }
    if (k < end) {
        int s = g_eidx[k];
        uint2 v = *(const uint2*)(g_y2h + (size_t)s * 40 + q * 4);
        float2 p;
        p = __half22float2(*(__half2*)&v.x); acc.x += p.x; acc.y += p.y;
        p = __half22float2(*(__half2*)&v.y); acc.z += p.x; acc.w += p.y;
    }
    unsigned m = 0xFFFFFFFFu;
    float ax = acc.x + __shfl_sync(m, acc.x, lane + 10) + __shfl_sync(m, acc.x, lane + 20);
    float ay = acc.y + __shfl_sync(m, acc.y, lane + 10) + __shfl_sync(m, acc.y, lane + 20);
    float az = acc.z + __shfl_sync(m, acc.z, lane + 10) + __shfl_sync(m, acc.z, lane + 20);
    float aw = acc.w + __shfl_sync(m, acc.w, lane + 10) + __shfl_sync(m, acc.w, lane + 20);
    if (lane < 10) {
        float di = g_dinv[n];
        float4 b = ((const float4*)b2)[q];
        float4 r;
        r.x = fmaf(di, ax, b.x);
        r.y = fmaf(di, ay, b.y);
        r.z = fmaf(di, az, b.z);
        r.w = fmaf(di, aw, b.w);
        ((float4*)(out + (size_t)n * 40))[q] = r;
    }
}

extern "C" void kernel_launch(void* const* d_in, const int* in_sizes, int n_in,
                              void* d_out, int out_size) {
    const float* x    = (const float*)d_in[0];
    const int*   ei32 = (const int*)d_in[1];
    const float* W1   = (const float*)d_in[2];
    const float* b1   = (const float*)d_in[3];
    const float* W2   = (const float*)d_in[4];
    const float* b2   = (const float*)d_in[5];
    float*       out  = (float*)d_out;

    const int nn = in_sizes[0] / 128;     // 50000
    const int ne = in_sizes[1] / 2;       // 640000
    const int nb = (nn + 255) / 256;      // 196 — covers nn AND 128*128 weight elems

    const int smem1 = (2 * 128 * 136 + 2 * 128 * 136) * 2;   // 139264 B
    const int smem2 = (2 * 128 * 136 + 2 * 128 * 56) * 2;    //  98304 B
    cudaFuncSetAttribute(k_gemm1, cudaFuncAttributeMaxDynamicSharedMemorySize, smem1);
    cudaFuncSetAttribute(k_mid,   cudaFuncAttributeMaxDynamicSharedMemorySize, smem2);

    k_init<<<nb, 256>>>(ei32, nn);
    k_count<<<(ne + 255) / 256, 256>>>(ei32, ne, nn);
    k_scan1<<<nb, 256>>>(nn);
    k_scan2<<<1, 256>>>(nb);
    k_scan3<<<nb, 256>>>(W1, W2, nn, ne);   // FIX: nb blocks (was 64 — left nodes >=16384 uninitialized)
    k_fill<<<(ne + 255) / 256, 256>>>(ei32, ne, nn);

    int gblk = (nn + 127) / 128;
    k_gemm1<<<gblk, 256, smem1>>>(x, nn);
    k_mid<<<gblk, 256, smem2>>>(b1, nn);
    k_gather2<<<(nn + 7) / 8, 256>>>(out, b2, nn);
}

// round 16
// speedup vs baseline: 1.1137x; 1.1137x over previous
#include <cuda_runtime.h>
#include <cuda_bf16.h>
#include <cuda_fp16.h>
#include <stdint.h>

// GCN 2-layer, N=50000, E=640000, 128 -> 128(relu) -> 40.
// bf16x3 tensor-core GEMMs, fp16 feature storage for gathers, CSR warp-gather.
// Gathers run as standalone high-occupancy kernels (latency-bound phase).

#define NN 50000
#define NE 640000

// ---- scratch (device globals; allocation forbidden) ----
__device__ int   g_is32;
__device__ int   g_eidx[NE];
__device__ int   g_rowptr[NN + 1];
__device__ int   g_cursor[NN];
__device__ int   g_rowtmp[NN];
__device__ int   g_bsum[256];
__device__ int   g_boff[256];
__device__ int   g_deg[NN];
__device__ float g_dinv[NN];
__device__ __align__(16) __half g_y1h[NN * 128];   // layer1 scaled GEMM out (fp16)
__device__ __align__(16) float  g_h  [NN * 128];   // hidden (fp32)
__device__ __align__(16) __half g_y2h[NN * 40];    // layer2 scaled GEMM out (fp16)
__device__ __align__(4) __nv_bfloat16 g_W1h[128 * 128], g_W1l[128 * 128];
__device__ __align__(4) __nv_bfloat16 g_W2h[128 * 40],  g_W2l[128 * 40];

// ---------------- prologue ----------------
__global__ void k_init(const int* __restrict__ ei32, int nn) {
    int t = threadIdx.x;
    int i = blockIdx.x * 256 + t;
    if (i < nn) g_deg[i] = 0;
    if (blockIdx.x == 0) {
        __shared__ int any;
        if (t == 0) any = 0;
        __syncthreads();
        if (ei32[2 * t + 1] != 0) any = 1;   // int64 high halves all 0
        __syncthreads();
        if (t == 0) g_is32 = any;
    }
}

__global__ void k_count(const int* __restrict__ ei32, int ne, int nn) {
    int e = blockIdx.x * blockDim.x + threadIdx.x;
    if (e >= ne) return;
    int d = g_is32 ? ei32[ne + e] : ei32[2 * ne + 2 * e];
    d = ((unsigned)d < (unsigned)nn) ? d : 0;
    atomicAdd(&g_deg[d], 1);
}

__device__ __forceinline__ int blk_scan_incl(int v, int t) {
    int x = v;
#pragma unroll
    for (int o = 1; o < 32; o <<= 1) {
        int y = __shfl_up_sync(0xFFFFFFFFu, x, o);
        if ((t & 31) >= o) x += y;
    }
    __shared__ int ws[8];
    if ((t & 31) == 31) ws[t >> 5] = x;
    __syncthreads();
    if (t < 8) {
        int y = ws[t], z = y;
#pragma unroll
        for (int o = 1; o < 8; o <<= 1) {
            int u = __shfl_up_sync(0xFFu, z, o);
            if (t >= o) z += u;
        }
        ws[t] = z - y;
    }
    __syncthreads();
    return x + ws[t >> 5];
}

__global__ void k_scan1(int nn) {
    int t = threadIdx.x;
    int i = blockIdx.x * 256 + t;
    int v = (i < nn) ? g_deg[i] : 0;
    int incl = blk_scan_incl(v, t);
    if (i < nn) g_rowtmp[i] = incl - v;
    if (t == 255) g_bsum[blockIdx.x] = incl;
}

__global__ void k_scan2(int nb) {
    int t = threadIdx.x;
    int v = (t < nb) ? g_bsum[t] : 0;
    int incl = blk_scan_incl(v, t);
    g_boff[t] = incl - v;
}

// rowptr/cursor/dinv + weight split (fused). Launch with >= max(nn, 16384) threads.
__global__ void k_scan3(const float* __restrict__ W1, const float* __restrict__ W2,
                        int nn, int ne) {
    int i = blockIdx.x * blockDim.x + threadIdx.x;
    if (i < nn) {
        int rp = g_rowtmp[i] + g_boff[i >> 8];
        g_rowptr[i] = rp;
        g_cursor[i] = rp;
        g_dinv[i] = rsqrtf((float)(g_deg[i] + 1));
    }
    if (i == 0) g_rowptr[nn] = ne;
    if (i < 128 * 128) {
        float v = W1[i];
        __nv_bfloat16 h = __float2bfloat16(v);
        g_W1h[i] = h;
        g_W1l[i] = __float2bfloat16(v - __bfloat162float(h));
    }
    if (i < 128 * 40) {
        float v = W2[i];
        __nv_bfloat16 h = __float2bfloat16(v);
        g_W2h[i] = h;
        g_W2l[i] = __float2bfloat16(v - __bfloat162float(h));
    }
}

__global__ void k_fill(const int* __restrict__ ei32, int ne, int nn) {
    int e = blockIdx.x * blockDim.x + threadIdx.x;
    if (e >= ne) return;
    int s, d;
    if (g_is32) { s = ei32[e];     d = ei32[ne + e]; }
    else        { s = ei32[2 * e]; d = ei32[2 * ne + 2 * e]; }
    s = ((unsigned)s < (unsigned)nn) ? s : 0;
    d = ((unsigned)d < (unsigned)nn) ? d : 0;
    int pos = atomicAdd(&g_cursor[d], 1);
    g_eidx[pos] = s;
}

// ---------------- MMA helpers ----------------
__device__ __forceinline__ uint32_t s2u(const void* p) {
    return (uint32_t)__cvta_generic_to_shared(p);
}
__device__ __forceinline__ uint32_t pack2(float a, float b) {
    __nv_bfloat162 t = __floats2bfloat162_rn(a, b);
    return *(uint32_t*)&t;
}
__device__ __forceinline__ void ldsm_x4(uint32_t a[4], uint32_t addr) {
    asm volatile("ldmatrix.sync.aligned.m8n8.x4.shared.b16 {%0,%1,%2,%3},[%4];"
                 : "=r"(a[0]), "=r"(a[1]), "=r"(a[2]), "=r"(a[3]) : "r"(addr));
}
__device__ __forceinline__ void ldsm_x2t(uint32_t b[2], uint32_t addr) {
    asm volatile("ldmatrix.sync.aligned.m8n8.x2.trans.shared.b16 {%0,%1},[%2];"
                 : "=r"(b[0]), "=r"(b[1]) : "r"(addr));
}
__device__ __forceinline__ void mma16816(float d[4], const uint32_t a[4], const uint32_t b[2]) {
    asm volatile("mma.sync.aligned.m16n8k16.row.col.f32.bf16.bf16.f32 "
                 "{%0,%1,%2,%3},{%4,%5,%6,%7},{%8,%9},{%0,%1,%2,%3};"
                 : "+f"(d[0]), "+f"(d[1]), "+f"(d[2]), "+f"(d[3])
                 : "r"(a[0]), "r"(a[1]), "r"(a[2]), "r"(a[3]), "r"(b[0]), "r"(b[1]));
}

// core MMA over pre-filled smem tiles: out fp16, scaled by dinv
template <int NW, int XP, int WP>
__device__ __forceinline__ void mma_tile_store(
    const __nv_bfloat16* xh, const __nv_bfloat16* xl,
    const __nv_bfloat16* wh, const __nv_bfloat16* wl,
    __half* outp, int m_base, int nn, int tid)
{
    constexpr int NT = NW / 8;
    int warp = tid >> 5, lane = tid & 31;
    int mrow = warp * 16;

    float d[NT][4];
#pragma unroll
    for (int t = 0; t < NT; t++) { d[t][0] = d[t][1] = d[t][2] = d[t][3] = 0.f; }

    uint32_t xh_b = s2u(xh), xl_b = s2u(xl), wh_b = s2u(wh), wl_b = s2u(wl);
    uint32_t a_off = ((mrow + (lane & 15)) * XP + (lane >> 4) * 8) * 2;
    uint32_t b_lrow = (lane & 15);

#pragma unroll
    for (int ks = 0; ks < 8; ks++) {
        uint32_t ah[4], al[4];
        ldsm_x4(ah, xh_b + a_off + ks * 32);
        ldsm_x4(al, xl_b + a_off + ks * 32);
        uint32_t brow = ((ks * 16 + b_lrow) * WP) * 2;
#pragma unroll
        for (int nt = 0; nt < NT; nt++) {
            uint32_t bh[2], bl[2];
            ldsm_x2t(bh, wh_b + brow + nt * 16);
            ldsm_x2t(bl, wl_b + brow + nt * 16);
            mma16816(d[nt], ah, bh);
            mma16816(d[nt], ah, bl);
            mma16816(d[nt], al, bh);
        }
    }

    int r0 = m_base + mrow + (lane >> 2);
    int r1 = r0 + 8;
    int c0 = (lane & 3) * 2;
    float di0 = (r0 < nn) ? g_dinv[r0] : 0.f;
    float di1 = (r1 < nn) ? g_dinv[r1] : 0.f;
#pragma unroll
    for (int nt = 0; nt < NT; nt++) {
        int col = nt * 8 + c0;
        if (r0 < nn)
            *(__half2*)&outp[(size_t)r0 * NW + col] = __floats2half2_rn(d[nt][0] * di0, d[nt][1] * di0);
        if (r1 < nn)
            *(__half2*)&outp[(size_t)r1 * NW + col] = __floats2half2_rn(d[nt][2] * di1, d[nt][3] * di1);
    }
}

// load fp32 tile row-block + split to bf16 hi/lo smem (shared by both GEMMs)
template <int XP>
__device__ __forceinline__ void load_split_x(
    const float* __restrict__ in, __nv_bfloat16* xh, __nv_bfloat16* xl,
    int m_base, int nn, int tid)
{
    for (int i = tid; i < 128 * 32; i += 256) {
        int r = i >> 5, cq = i & 31;
        int row = m_base + r;
        float4 v = make_float4(0.f, 0.f, 0.f, 0.f);
        if (row < nn) v = ((const float4*)(in + (size_t)row * 128))[cq];
        float hx = __bfloat162float(__float2bfloat16(v.x));
        float hy = __bfloat162float(__float2bfloat16(v.y));
        float hz = __bfloat162float(__float2bfloat16(v.z));
        float hw = __bfloat162float(__float2bfloat16(v.w));
        *(uint2*)&xh[r * XP + cq * 4] = make_uint2(pack2(v.x, v.y), pack2(v.z, v.w));
        *(uint2*)&xl[r * XP + cq * 4] =
            make_uint2(pack2(v.x - hx, v.y - hy), pack2(v.z - hz, v.w - hw));
    }
}

// ---------------- layer 1 GEMM: y1h = fp16(dinv * (x @ W1)) ----------------
__global__ void k_gemm1(const float* __restrict__ x, int nn) {
    constexpr int XP = 136, WP = 136;
    extern __shared__ __nv_bfloat16 sm[];
    __nv_bfloat16* xh = sm;
    __nv_bfloat16* xl = xh + 128 * XP;
    __nv_bfloat16* wh = xl + 128 * XP;
    __nv_bfloat16* wl = wh + 128 * WP;

    int tid = threadIdx.x;
    int m_base = blockIdx.x * 128;

    const uint32_t* wsh = (const uint32_t*)g_W1h;
    const uint32_t* wsl = (const uint32_t*)g_W1l;
    for (int i = tid; i < 128 * 128 / 2; i += 256) {
        int r = (2 * i) >> 7, c = (2 * i) & 127;
        *(uint32_t*)&wh[r * WP + c] = wsh[i];
        *(uint32_t*)&wl[r * WP + c] = wsl[i];
    }
    load_split_x<XP>(x, xh, xl, m_base, nn, tid);
    __syncthreads();
    mma_tile_store<128, XP, WP>(xh, xl, wh, wl, g_y1h, m_base, nn, tid);
}

// ---------------- layer 1 gather: h = relu(dinv*(y1[n] + sum y1[src]) + b1) ----------------
// warp per node, no smem, full occupancy; lane owns 4 halves (uint2) per edge row.
__global__ void k_gather1(const float* __restrict__ b1, int nn) {
    int warp = (blockIdx.x * blockDim.x + threadIdx.x) >> 5;
    if (warp >= nn) return;
    int lane = threadIdx.x & 31;
    int n = warp;
    int beg = g_rowptr[n], end = g_rowptr[n + 1];

    uint2 sv = *(const uint2*)(g_y1h + (size_t)n * 128 + lane * 4);   // self loop
    float2 a0 = __half22float2(*(__half2*)&sv.x);
    float2 a1 = __half22float2(*(__half2*)&sv.y);
    float4 acc = make_float4(a0.x, a0.y, a1.x, a1.y);

    int k = beg;
    for (; k + 3 < end; k += 4) {                                     // 4 loads in flight
        int s0 = g_eidx[k], s1 = g_eidx[k + 1], s2 = g_eidx[k + 2], s3 = g_eidx[k + 3];
        uint2 v0 = *(const uint2*)(g_y1h + (size_t)s0 * 128 + lane * 4);
        uint2 v1 = *(const uint2*)(g_y1h + (size_t)s1 * 128 + lane * 4);
        uint2 v2 = *(const uint2*)(g_y1h + (size_t)s2 * 128 + lane * 4);
        uint2 v3 = *(const uint2*)(g_y1h + (size_t)s3 * 128 + lane * 4);
        float2 p;
        p = __half22float2(*(__half2*)&v0.x); acc.x += p.x; acc.y += p.y;
        p = __half22float2(*(__half2*)&v0.y); acc.z += p.x; acc.w += p.y;
        p = __half22float2(*(__half2*)&v1.x); acc.x += p.x; acc.y += p.y;
        p = __half22float2(*(__half2*)&v1.y); acc.z += p.x; acc.w += p.y;
        p = __half22float2(*(__half2*)&v2.x); acc.x += p.x; acc.y += p.y;
        p = __half22float2(*(__half2*)&v2.y); acc.z += p.x; acc.w += p.y;
        p = __half22float2(*(__half2*)&v3.x); acc.x += p.x; acc.y += p.y;
        p = __half22float2(*(__half2*)&v3.y); acc.z += p.x; acc.w += p.y;
    }
    for (; k < end; k++) {
        int s = g_eidx[k];
        uint2 v = *(const uint2*)(g_y1h + (size_t)s * 128 + lane * 4);
        float2 p;
        p = __half22float2(*(__half2*)&v.x); acc.x += p.x; acc.y += p.y;
        p = __half22float2(*(__half2*)&v.y); acc.z += p.x; acc.w += p.y;
    }
    float di = g_dinv[n];
    float4 b = ((const float4*)b1)[lane];
    float4 h;
    h.x = fmaxf(fmaf(di, acc.x, b.x), 0.f);
    h.y = fmaxf(fmaf(di, acc.y, b.y), 0.f);
    h.z = fmaxf(fmaf(di, acc.z, b.z), 0.f);
    h.w = fmaxf(fmaf(di, acc.w, b.w), 0.f);
    ((float4*)(g_h + (size_t)n * 128))[lane] = h;
}

// ---------------- layer 2 GEMM: y2h = fp16(dinv * (h @ W2)) ----------------
__global__ void k_gemm2(int nn) {
    constexpr int XP = 136, WP = 56, NW = 40;
    extern __shared__ __nv_bfloat16 sm[];
    __nv_bfloat16* xh = sm;
    __nv_bfloat16* xl = xh + 128 * XP;
    __nv_bfloat16* wh = xl + 128 * XP;
    __nv_bfloat16* wl = wh + 128 * WP;

    int tid = threadIdx.x;
    int m_base = blockIdx.x * 128;

    const uint32_t* wsh = (const uint32_t*)g_W2h;
    const uint32_t* wsl = (const uint32_t*)g_W2l;
    for (int i = tid; i < 128 * NW / 2; i += 256) {
        int r = (2 * i) / NW, c = (2 * i) % NW;
        *(uint32_t*)&wh[r * WP + c] = wsh[i];
        *(uint32_t*)&wl[r * WP + c] = wsl[i];
    }
    load_split_x<XP>(g_h, xh, xl, m_base, nn, tid);
    __syncthreads();
    mma_tile_store<NW, XP, WP>(xh, xl, wh, wl, g_y2h, m_base, nn, tid);
}

// ---------------- layer 2 gather: out = dinv*(y2[n] + sum y2[src]) + b2 ----------------
__global__ void k_gather2(float* __restrict__ out, const float* __restrict__ b2, int nn) {
    int warp = (blockIdx.x * blockDim.x + threadIdx.x) >> 5;
    if (warp >= nn) return;
    int lane = threadIdx.x & 31;
    int n = warp;
    int beg = g_rowptr[n], end = g_rowptr[n + 1];
    int sub = lane / 10;
    int q = lane % 10;
    float4 acc = make_float4(0.f, 0.f, 0.f, 0.f);
    if (sub == 0) {
        uint2 v = *(const uint2*)(g_y2h + (size_t)n * 40 + q * 4);
        float2 p0 = __half22float2(*(__half2*)&v.x);
        float2 p1 = __half22float2(*(__half2*)&v.y);
        acc = make_float4(p0.x, p0.y, p1.x, p1.y);
    }
    int k = (sub < 3) ? (beg + sub) : end;
    for (; k + 3 < end; k += 6) {
        int s0 = g_eidx[k], s1 = g_eidx[k + 3];
        uint2 v0 = *(const uint2*)(g_y2h + (size_t)s0 * 40 + q * 4);
        uint2 v1 = *(const uint2*)(g_y2h + (size_t)s1 * 40 + q * 4);
        float2 p;
        p = __half22float2(*(__half2*)&v0.x); acc.x += p.x; acc.y += p.y;
        p = __half22float2(*(__half2*)&v0.y); acc.z += p.x; acc.w += p.y;
        p = __half22float2(*(__half2*)&v1.x); acc.x += p.x; acc.y += p.y;
        p = __half22float2(*(__half2*)&v1.y); acc.z += p.x; acc.w += p.y;
    }
    if (k < end) {
        int s = g_eidx[k];
        uint2 v = *(const uint2*)(g_y2h + (size_t)s * 40 + q * 4);
        float2 p;
        p = __half22float2(*(__half2*)&v.x); acc.x += p.x; acc.y += p.y;
        p = __half22float2(*(__half2*)&v.y); acc.z += p.x; acc.w += p.y;
    }
    unsigned m = 0xFFFFFFFFu;
    float ax = acc.x + __shfl_sync(m, acc.x, lane + 10) + __shfl_sync(m, acc.x, lane + 20);
    float ay = acc.y + __shfl_sync(m, acc.y, lane + 10) + __shfl_sync(m, acc.y, lane + 20);
    float az = acc.z + __shfl_sync(m, acc.z, lane + 10) + __shfl_sync(m, acc.z, lane + 20);
    float aw = acc.w + __shfl_sync(m, acc.w, lane + 10) + __shfl_sync(m, acc.w, lane + 20);
    if (lane < 10) {
        float di = g_dinv[n];
        float4 b = ((const float4*)b2)[q];
        float4 r;
        r.x = fmaf(di, ax, b.x);
        r.y = fmaf(di, ay, b.y);
        r.z = fmaf(di, az, b.z);
        r.w = fmaf(di, aw, b.w);
        ((float4*)(out + (size_t)n * 40))[q] = r;
    }
}

extern "C" void kernel_launch(void* const* d_in, const int* in_sizes, int n_in,
                              void* d_out, int out_size) {
    const float* x    = (const float*)d_in[0];
    const int*   ei32 = (const int*)d_in[1];
    const float* W1   = (const float*)d_in[2];
    const float* b1   = (const float*)d_in[3];
    const float* W2   = (const float*)d_in[4];
    const float* b2   = (const float*)d_in[5];
    float*       out  = (float*)d_out;

    const int nn = in_sizes[0] / 128;     // 50000
    const int ne = in_sizes[1] / 2;       // 640000
    const int nb = (nn + 255) / 256;      // 196 — covers nn and 128*128 weight elems

    const int smem1 = (2 * 128 * 136 + 2 * 128 * 136) * 2;   // 139264 B
    const int smem2 = (2 * 128 * 136 + 2 * 128 * 56) * 2;    //  98304 B
    cudaFuncSetAttribute(k_gemm1, cudaFuncAttributeMaxDynamicSharedMemorySize, smem1);
    cudaFuncSetAttribute(k_gemm2, cudaFuncAttributeMaxDynamicSharedMemorySize, smem2);

    k_init<<<nb, 256>>>(ei32, nn);
    k_count<<<(ne + 255) / 256, 256>>>(ei32, ne, nn);
    k_scan1<<<nb, 256>>>(nn);
    k_scan2<<<1, 256>>>(nb);
    k_scan3<<<nb, 256>>>(W1, W2, nn, ne);
    k_fill<<<(ne + 255) / 256, 256>>>(ei32, ne, nn);

    int gblk = (nn + 127) / 128;
    k_gemm1<<<gblk, 256, smem1>>>(x, nn);
    k_gather1<<<(nn + 7) / 8, 256>>>(b1, nn);
    k_gemm2<<<gblk, 256, smem2>>>(nn);
    k_gather2<<<(nn + 7) / 8, 256>>>(out, b2, nn);
}